// round 10
// baseline (speedup 1.0000x reference)
#include <cuda_runtime.h>
#include <cstdint>

// Problem constants
#define T_SEQ   2048
#define DMODEL  1024
#define NHEAD   16
#define DHEAD   64
#define BATCH   2
#define MROWS   (BATCH * T_SEQ)   // 4096

// ---------------------------------------------------------------------------
// Scratch (__device__ globals; allocation-free rule)
// q/k/v hold tf32-rounded values (rounded in GEMM epilogue)
// ---------------------------------------------------------------------------
__device__ float g_q[MROWS * DMODEL];
__device__ float g_k[MROWS * DMODEL];
__device__ float g_v[MROWS * DMODEL];
__device__ float g_att[MROWS * DMODEL];
__device__ float g_xr[MROWS * DMODEL];          // tf32-rounded x
__device__ float g_wt[4 * DMODEL * DMODEL];     // tf32-rounded weights (q,k,v,o)

// ---------------------------------------------------------------------------
// Helpers
// ---------------------------------------------------------------------------
__device__ __forceinline__ float to_tf32(float x) {
    unsigned r;
    asm("cvt.rna.tf32.f32 %0, %1;" : "=r"(r) : "f"(x));
    return __uint_as_float(r);
}

__device__ __forceinline__ uint32_t smem_u32(const void* p) {
    uint32_t a;
    asm("{ .reg .u64 t; cvta.to.shared.u64 t, %1; cvt.u32.u64 %0, t; }" : "=r"(a) : "l"(p));
    return a;
}

__device__ __forceinline__ void cp_async16(uint32_t saddr, const void* gptr) {
    asm volatile("cp.async.cg.shared.global [%0], [%1], 16;" :: "r"(saddr), "l"(gptr));
}
#define CP_COMMIT() asm volatile("cp.async.commit_group;" ::: "memory")
#define CP_WAIT(n)  asm volatile("cp.async.wait_group %0;" :: "n"(n) : "memory")

// mma.sync m16n8k8 row.col f32 += tf32*tf32
// A frag: a0=(g,tg) a1=(g+8,tg) a2=(g,tg+4) a3=(g+8,tg+4)
// B frag: b0=(k=tg,n=g) b1=(k=tg+4,n=g)
// C frag: c0=(g,2tg) c1=(g,2tg+1) c2=(g+8,2tg) c3=(g+8,2tg+1)
__device__ __forceinline__ void mma_tf32(float* c, const float* a, const float* b) {
    asm volatile(
        "mma.sync.aligned.m16n8k8.row.col.f32.tf32.tf32.f32 "
        "{%0,%1,%2,%3}, {%4,%5,%6,%7}, {%8,%9}, {%0,%1,%2,%3};\n"
        : "+f"(c[0]), "+f"(c[1]), "+f"(c[2]), "+f"(c[3])
        : "r"(__float_as_uint(a[0])), "r"(__float_as_uint(a[1])),
          "r"(__float_as_uint(a[2])), "r"(__float_as_uint(a[3])),
          "r"(__float_as_uint(b[0])), "r"(__float_as_uint(b[1])));
}

// ---------------------------------------------------------------------------
// Prep: round x / weights to tf32 once (layout unchanged [k][n])
// ---------------------------------------------------------------------------
__global__ void prep_x_kernel(const float* __restrict__ x) {
    int i = blockIdx.x * blockDim.x + threadIdx.x;
    float4 v = ((const float4*)x)[i];
    v.x = to_tf32(v.x); v.y = to_tf32(v.y); v.z = to_tf32(v.z); v.w = to_tf32(v.w);
    ((float4*)g_xr)[i] = v;
}

__global__ void prep_w_kernel(const float* __restrict__ Wq, const float* __restrict__ Wk,
                              const float* __restrict__ Wv, const float* __restrict__ Wo) {
    int z = blockIdx.y;
    const float* W = (z == 0) ? Wq : (z == 1) ? Wk : (z == 2) ? Wv : Wo;
    int i = blockIdx.x * blockDim.x + threadIdx.x;
    float4 v = ((const float4*)W)[i];
    v.x = to_tf32(v.x); v.y = to_tf32(v.y); v.z = to_tf32(v.z); v.w = to_tf32(v.w);
    ((float4*)(g_wt + (size_t)z * DMODEL * DMODEL))[i] = v;
}

// ---------------------------------------------------------------------------
// Pipelined tf32 GEMM:  C[4096,1024] = A[4096,1024] @ W[1024,1024]
// CTA tile 128x256x64, 2-stage cp.async ring, 512 threads (16 warps, 2m x 8n,
// warp tile 64x32). 16 iterations, next chunk in flight during compute.
// qkv_mode=1: A=g_xr, W=g_wt[z], dst=g_q/g_k/g_v scattered to [B,H,T,DH],
//             values tf32-rounded on store (for the attention kernel).
// qkv_mode=0: A=g_att, W=g_wt[3], dst=out row-major, full fp32.
// ---------------------------------------------------------------------------
#define GBM 128
#define GBN 256
#define GBK 64
#define ASTR 68          // 64 + 4 pad: (4g+tg) banks distinct for A-frag reads
#define BSTR 264         // (8tg+g) banks distinct for B-frag reads
#define NSTAGE 2
#define A_STAGE (GBM * ASTR)                    // 8704 floats
#define B_STAGE (GBK * BSTR)                    // 16896 floats
#define STAGE_FLOATS (A_STAGE + B_STAGE)        // 25600 floats
#define GEMM_SMEM (NSTAGE * STAGE_FLOATS * 4)   // 204800 bytes

__global__ __launch_bounds__(512, 1)
void gemm_tf32_pipe_kernel(float* __restrict__ out, int qkv_mode)
{
    extern __shared__ float sm[];
    const uint32_t sb = smem_u32(sm);

    const int tid = threadIdx.x;
    const int warp = tid >> 5, lane = tid & 31;
    const int g = lane >> 2, tg = lane & 3;
    const int wm = (warp & 1) * 64;       // 2 warps along M
    const int wn = (warp >> 1) * 32;      // 8 warps along N
    const int z = blockIdx.z;
    const int row0 = blockIdx.y * GBM;
    const int col0 = blockIdx.x * GBN;

    const float* A  = qkv_mode ? g_xr : g_att;
    const float* Wt = g_wt + (size_t)(qkv_mode ? z : 3) * DMODEL * DMODEL;

    float acc[4][4][4];
#pragma unroll
    for (int mi = 0; mi < 4; mi++)
#pragma unroll
        for (int ni = 0; ni < 4; ni++)
#pragma unroll
            for (int i = 0; i < 4; i++) acc[mi][ni][i] = 0.f;

    // ---- async chunk loader (512 threads), K-chunk of 64 ----
    auto load_chunk = [&](int c, int s) {
        const int kt = c * GBK;
        const uint32_t abase = sb + (uint32_t)(s * STAGE_FLOATS) * 4;
        const uint32_t bbase = abase + A_STAGE * 4;
        // A: 128 rows x 16 segs = 2048, 4 per thread
#pragma unroll
        for (int it = 0; it < 4; it++) {
            int i = tid + it * 512;
            int row = i >> 4, seg = i & 15;
            cp_async16(abase + (uint32_t)(row * ASTR + seg * 4) * 4,
                       A + (size_t)(row0 + row) * DMODEL + kt + seg * 4);
        }
        // B: 64 rows x 64 segs = 4096, 8 per thread
#pragma unroll
        for (int it = 0; it < 8; it++) {
            int i = tid + it * 512;
            int row = i >> 6, seg = i & 63;
            cp_async16(bbase + (uint32_t)(row * BSTR + seg * 4) * 4,
                       Wt + (size_t)(kt + row) * DMODEL + col0 + seg * 4);
        }
        CP_COMMIT();
    };

    // ---- compute one 64-deep K-chunk from stage s ----
    auto compute_chunk = [&](int s) {
        const float* As_ = sm + s * STAGE_FLOATS;
        const float* Bs_ = As_ + A_STAGE;
#pragma unroll
        for (int ks = 0; ks < 8; ks++) {
            float a[4][4], b[4][2];
#pragma unroll
            for (int mi = 0; mi < 4; mi++) {
                int r = wm + mi * 16 + g;
                a[mi][0] = As_[r * ASTR + ks * 8 + tg];
                a[mi][1] = As_[(r + 8) * ASTR + ks * 8 + tg];
                a[mi][2] = As_[r * ASTR + ks * 8 + tg + 4];
                a[mi][3] = As_[(r + 8) * ASTR + ks * 8 + tg + 4];
            }
#pragma unroll
            for (int ni = 0; ni < 4; ni++) {
                int c = wn + ni * 8 + g;
                b[ni][0] = Bs_[(ks * 8 + tg) * BSTR + c];
                b[ni][1] = Bs_[(ks * 8 + tg + 4) * BSTR + c];
            }
#pragma unroll
            for (int mi = 0; mi < 4; mi++)
#pragma unroll
                for (int ni = 0; ni < 4; ni++)
                    mma_tf32(acc[mi][ni], a[mi], b[ni]);
        }
    };

    const int NCHUNK = DMODEL / GBK;   // 16
    load_chunk(0, 0);

    for (int i = 0; i < NCHUNK; i++) {
        if (i + 1 < NCHUNK) { load_chunk(i + 1, (i + 1) & 1); CP_WAIT(1); }
        else                { CP_WAIT(0); }
        __syncthreads();                 // chunk i visible to all warps
        compute_chunk(i & 1);
        __syncthreads();                 // stage free before next overwrite
    }

    // ---- epilogue ----
    float* dstq = (z == 0) ? g_q : (z == 1) ? g_k : g_v;
#pragma unroll
    for (int mi = 0; mi < 4; mi++) {
        const int r0 = row0 + wm + mi * 16 + g;
        const int r1 = r0 + 8;
#pragma unroll
        for (int ni = 0; ni < 4; ni++) {
            const int c = col0 + wn + ni * 8 + 2 * tg;
            if (qkv_mode) {
                // round to tf32 here so the attention kernel loads raw bits
                float2 v0 = make_float2(to_tf32(acc[mi][ni][0]), to_tf32(acc[mi][ni][1]));
                float2 v1 = make_float2(to_tf32(acc[mi][ni][2]), to_tf32(acc[mi][ni][3]));
                const int hh = c >> 6, dh = c & (DHEAD - 1);
                const int b0 = r0 >> 11, t0 = r0 & (T_SEQ - 1);
                const int b1 = r1 >> 11, t1 = r1 & (T_SEQ - 1);
                *(float2*)&dstq[(((size_t)(b0 * NHEAD + hh)) * T_SEQ + t0) * DHEAD + dh] = v0;
                *(float2*)&dstq[(((size_t)(b1 * NHEAD + hh)) * T_SEQ + t1) * DHEAD + dh] = v1;
            } else {
                float2 v0 = make_float2(acc[mi][ni][0], acc[mi][ni][1]);
                float2 v1 = make_float2(acc[mi][ni][2], acc[mi][ni][3]);
                *(float2*)&out[(size_t)r0 * DMODEL + c] = v0;
                *(float2*)&out[(size_t)r1 * DMODEL + c] = v1;
            }
        }
    }
}

// ---------------------------------------------------------------------------
// Flash attention (causal), tf32 mma.sync, fp32 online softmax.
// 256 threads, Q tile 128 rows (8 warps x 16 rows), KV tile 64.
// DOUBLE-BUFFERED KV: load of tile j+1 is in flight during compute of tile j.
// Q fragments hoisted to registers (read once, reused across all KV iters).
// 1 CTA/SM (141KB smem, up to 256 regs). Grid 512 blocks, longest-qt-first.
// ---------------------------------------------------------------------------
#define QS 68
#define VS 72
// Qs[128*QS] K0 K1 [64*QS each] V0 V1 [64*VS each] Ps[128*QS]
#define ATTN_SMEM ((128 * QS + 2 * 64 * QS + 2 * 64 * VS + 128 * QS) * 4)  // 141312

__global__ __launch_bounds__(256, 1)
void attn_kernel()
{
    extern __shared__ float sm[];
    float* Qs = sm;                          // 128 x QS
    float* Kb[2], * Vb[2];
    Kb[0] = Qs + 128 * QS;
    Kb[1] = Kb[0] + 64 * QS;
    Vb[0] = Kb[1] + 64 * QS;
    Vb[1] = Vb[0] + 64 * VS;
    float* Ps = Vb[1] + 64 * VS;             // 128 x QS
    const uint32_t sb = smem_u32(sm);
    const uint32_t kb0 = sb + (uint32_t)(128 * QS) * 4;
    const uint32_t kstride = (uint32_t)(64 * QS) * 4;
    const uint32_t vb0 = kb0 + 2 * kstride;
    const uint32_t vstride = (uint32_t)(64 * VS) * 4;

    const int b = blockIdx.z, h = blockIdx.y;
    const int qt = (T_SEQ / 128 - 1) - (int)blockIdx.x;   // longest first (LPT)
    const int q0 = qt * 128;
    const int bh = b * NHEAD + h;
    const float* qptr = g_q + (size_t)bh * T_SEQ * DHEAD;
    const float* kptr = g_k + (size_t)bh * T_SEQ * DHEAD;
    const float* vptr = g_v + (size_t)bh * T_SEQ * DHEAD;

    const int tid = threadIdx.x;
    const int warp = tid >> 5, lane = tid & 31;
    const int g = lane >> 2, tg = lane & 3;
    const int wm = warp * 16;

    // prologue: Q tile (group 0), KV tile 0 (group 1)
#pragma unroll
    for (int it = 0; it < 8; it++) {
        int i = tid + it * 256;
        int row = i >> 4, seg = i & 15;
        cp_async16(sb + (uint32_t)(row * QS + seg * 4) * 4,
                   qptr + (size_t)(q0 + row) * DHEAD + seg * 4);
    }
    CP_COMMIT();
    {
        const uint32_t kb = kb0, vb = vb0;
#pragma unroll
        for (int it = 0; it < 4; it++) {
            int i = tid + it * 256;
            int row = i >> 4, seg = i & 15;
            cp_async16(kb + (uint32_t)(row * QS + seg * 4) * 4,
                       kptr + (size_t)row * DHEAD + seg * 4);
            cp_async16(vb + (uint32_t)(row * VS + seg * 4) * 4,
                       vptr + (size_t)row * DHEAD + seg * 4);
        }
        CP_COMMIT();
    }

    float qf[8][4];                          // Q fragments (filled at j==0)
    float o[8][4];
#pragma unroll
    for (int ni = 0; ni < 8; ni++)
#pragma unroll
        for (int i = 0; i < 4; i++) o[ni][i] = 0.f;
    float m0 = -1e30f, m1 = -1e30f, l0 = 0.f, l1 = 0.f;

    const int jn = 2 * qt + 2;               // KV tiles (causal)
    const int qrow0 = q0 + wm + g;
    const int qrow1 = qrow0 + 8;

    for (int j = 0; j < jn; j++) {
        const int p = j & 1;
        // issue KV(j+1) into the alternate buffers, then wait for KV(j)
        if (j + 1 < jn) {
            const uint32_t kb = kb0 + (uint32_t)(1 - p) * kstride;
            const uint32_t vb = vb0 + (uint32_t)(1 - p) * vstride;
            const float* kg = kptr + (size_t)(j + 1) * 64 * DHEAD;
            const float* vg = vptr + (size_t)(j + 1) * 64 * DHEAD;
#pragma unroll
            for (int it = 0; it < 4; it++) {
                int i = tid + it * 256;
                int row = i >> 4, seg = i & 15;
                cp_async16(kb + (uint32_t)(row * QS + seg * 4) * 4,
                           kg + (size_t)row * DHEAD + seg * 4);
                cp_async16(vb + (uint32_t)(row * VS + seg * 4) * 4,
                           vg + (size_t)row * DHEAD + seg * 4);
            }
            CP_COMMIT();
            CP_WAIT(1);
        } else {
            CP_WAIT(0);
        }
        __syncthreads();                     // KV(j) (and Q at j==0) visible

        if (j == 0) {
#pragma unroll
            for (int ks = 0; ks < 8; ks++) {
                qf[ks][0] = Qs[(wm + g) * QS + ks * 8 + tg];
                qf[ks][1] = Qs[(wm + g + 8) * QS + ks * 8 + tg];
                qf[ks][2] = Qs[(wm + g) * QS + ks * 8 + tg + 4];
                qf[ks][3] = Qs[(wm + g + 8) * QS + ks * 8 + tg + 4];
            }
        }

        const float* Ks = Kb[p];
        const float* Vs = Vb[p];

        // S = Q @ K^T  (warp: 16 q-rows x 64 keys)
        float s[8][4];
#pragma unroll
        for (int ni = 0; ni < 8; ni++)
#pragma unroll
            for (int i = 0; i < 4; i++) s[ni][i] = 0.f;

#pragma unroll
        for (int ks = 0; ks < 8; ks++) {
#pragma unroll
            for (int ni = 0; ni < 8; ni++) {
                float bf[2];
                bf[0] = Ks[(ni * 8 + g) * QS + ks * 8 + tg];
                bf[1] = Ks[(ni * 8 + g) * QS + ks * 8 + tg + 4];
                mma_tf32(s[ni], qf[ks], bf);
            }
        }

        // scale + causal mask
        const float scale = 0.125f;          // 1/sqrt(64)
#pragma unroll
        for (int ni = 0; ni < 8; ni++) {
            int kc = j * 64 + ni * 8 + 2 * tg;
            s[ni][0] = (kc     > qrow0) ? -1e30f : s[ni][0] * scale;
            s[ni][1] = (kc + 1 > qrow0) ? -1e30f : s[ni][1] * scale;
            s[ni][2] = (kc     > qrow1) ? -1e30f : s[ni][2] * scale;
            s[ni][3] = (kc + 1 > qrow1) ? -1e30f : s[ni][3] * scale;
        }

        // online softmax (4 lanes per row: xor 1,2)
        float mx0 = -1e30f, mx1 = -1e30f;
#pragma unroll
        for (int ni = 0; ni < 8; ni++) {
            mx0 = fmaxf(mx0, fmaxf(s[ni][0], s[ni][1]));
            mx1 = fmaxf(mx1, fmaxf(s[ni][2], s[ni][3]));
        }
        mx0 = fmaxf(mx0, __shfl_xor_sync(0xffffffffu, mx0, 1));
        mx0 = fmaxf(mx0, __shfl_xor_sync(0xffffffffu, mx0, 2));
        mx1 = fmaxf(mx1, __shfl_xor_sync(0xffffffffu, mx1, 1));
        mx1 = fmaxf(mx1, __shfl_xor_sync(0xffffffffu, mx1, 2));

        float mn0 = fmaxf(m0, mx0), mn1 = fmaxf(m1, mx1);
        float al0 = __expf(m0 - mn0), al1 = __expf(m1 - mn1);
        m0 = mn0; m1 = mn1;

        float sum0 = 0.f, sum1 = 0.f;
#pragma unroll
        for (int ni = 0; ni < 8; ni++) {
            float p00 = __expf(s[ni][0] - m0), p01 = __expf(s[ni][1] - m0);
            float p10 = __expf(s[ni][2] - m1), p11 = __expf(s[ni][3] - m1);
            sum0 += p00 + p01; sum1 += p10 + p11;
            Ps[(wm + g) * QS + ni * 8 + 2 * tg]         = to_tf32(p00);
            Ps[(wm + g) * QS + ni * 8 + 2 * tg + 1]     = to_tf32(p01);
            Ps[(wm + g + 8) * QS + ni * 8 + 2 * tg]     = to_tf32(p10);
            Ps[(wm + g + 8) * QS + ni * 8 + 2 * tg + 1] = to_tf32(p11);
        }
        sum0 += __shfl_xor_sync(0xffffffffu, sum0, 1);
        sum0 += __shfl_xor_sync(0xffffffffu, sum0, 2);
        sum1 += __shfl_xor_sync(0xffffffffu, sum1, 1);
        sum1 += __shfl_xor_sync(0xffffffffu, sum1, 2);
        l0 = l0 * al0 + sum0;
        l1 = l1 * al1 + sum1;

#pragma unroll
        for (int ni = 0; ni < 8; ni++) {
            o[ni][0] *= al0; o[ni][1] *= al0;
            o[ni][2] *= al1; o[ni][3] *= al1;
        }
        __syncwarp();                        // P rows are warp-private

        // O += P @ V
#pragma unroll
        for (int ks = 0; ks < 8; ks++) {
            float a[4];
            a[0] = Ps[(wm + g) * QS + ks * 8 + tg];
            a[1] = Ps[(wm + g + 8) * QS + ks * 8 + tg];
            a[2] = Ps[(wm + g) * QS + ks * 8 + tg + 4];
            a[3] = Ps[(wm + g + 8) * QS + ks * 8 + tg + 4];
#pragma unroll
            for (int ni = 0; ni < 8; ni++) {
                float bf[2];
                bf[0] = Vs[(ks * 8 + tg) * VS + ni * 8 + g];
                bf[1] = Vs[(ks * 8 + tg + 4) * VS + ni * 8 + g];
                mma_tf32(o[ni], a, bf);
            }
        }
        __syncthreads();                     // KV(j)/P reads done before overwrite
    }

    // epilogue: normalize, tf32-round, scatter to [B*T, D]
    const float inv0 = 1.f / l0, inv1 = 1.f / l1;
#pragma unroll
    for (int ni = 0; ni < 8; ni++) {
        int c = h * DHEAD + ni * 8 + 2 * tg;
        g_att[((size_t)b * T_SEQ + qrow0) * DMODEL + c]     = to_tf32(o[ni][0] * inv0);
        g_att[((size_t)b * T_SEQ + qrow0) * DMODEL + c + 1] = to_tf32(o[ni][1] * inv0);
        g_att[((size_t)b * T_SEQ + qrow1) * DMODEL + c]     = to_tf32(o[ni][2] * inv1);
        g_att[((size_t)b * T_SEQ + qrow1) * DMODEL + c + 1] = to_tf32(o[ni][3] * inv1);
    }
}

// ---------------------------------------------------------------------------
// kernel_launch: x, mask(causal hard-coded), Wq, Wk, Wv, Wo
// ---------------------------------------------------------------------------
extern "C" void kernel_launch(void* const* d_in, const int* in_sizes, int n_in,
                              void* d_out, int out_size)
{
    (void)in_sizes; (void)n_in; (void)out_size;
    const float* x  = (const float*)d_in[0];
    const float* Wq = (const float*)d_in[2];
    const float* Wk = (const float*)d_in[3];
    const float* Wv = (const float*)d_in[4];
    const float* Wo = (const float*)d_in[5];
    float* out = (float*)d_out;

    // prep: tf32-round inputs once
    prep_x_kernel<<<(MROWS * DMODEL / 4) / 256, 256>>>(x);
    prep_w_kernel<<<dim3((DMODEL * DMODEL / 4) / 256, 4), 256>>>(Wq, Wk, Wv, Wo);

    cudaFuncSetAttribute(gemm_tf32_pipe_kernel,
                         cudaFuncAttributeMaxDynamicSharedMemorySize, GEMM_SMEM);

    // fused QKV projections
    gemm_tf32_pipe_kernel<<<dim3(DMODEL / GBN, MROWS / GBM, 3), 512, GEMM_SMEM>>>(nullptr, 1);

    cudaFuncSetAttribute(attn_kernel,
                         cudaFuncAttributeMaxDynamicSharedMemorySize, ATTN_SMEM);
    attn_kernel<<<dim3(T_SEQ / 128, NHEAD, BATCH), 256, ATTN_SMEM>>>();

    // output projection
    gemm_tf32_pipe_kernel<<<dim3(DMODEL / GBN, MROWS / GBM, 1), 512, GEMM_SMEM>>>(out, 0);
}

// round 11
// speedup vs baseline: 1.2184x; 1.2184x over previous
#include <cuda_runtime.h>
#include <cstdint>

// Problem constants
#define T_SEQ   2048
#define DMODEL  1024
#define NHEAD   16
#define DHEAD   64
#define BATCH   2
#define MROWS   (BATCH * T_SEQ)   // 4096

// pair-interleave permutation within 8-element groups: c -> 2*(c&3) + (c>>2)
// pos 2c holds elem c, pos 2c+1 holds elem c+4  => (tg, tg+4) adjacent
#define PM8(c) ((((c) & 3) << 1) | (((c) >> 2) & 1))

// ---------------------------------------------------------------------------
// Scratch (__device__ globals; allocation-free rule)
// g_q/g_k: [B,H,T,DH] with dh-dim PM8-permuted, tf32-rounded
// g_v:     [B,H,DH,T] (transposed) with t-dim PM8-permuted, tf32-rounded
// ---------------------------------------------------------------------------
__device__ float g_q[MROWS * DMODEL];
__device__ float g_k[MROWS * DMODEL];
__device__ float g_v[MROWS * DMODEL];
__device__ float g_att[MROWS * DMODEL];
__device__ float g_xr[MROWS * DMODEL];          // tf32-rounded x
__device__ float g_wt[4 * DMODEL * DMODEL];     // tf32-rounded weights (q,k,v,o)

// ---------------------------------------------------------------------------
// Helpers
// ---------------------------------------------------------------------------
__device__ __forceinline__ float to_tf32(float x) {
    unsigned r;
    asm("cvt.rna.tf32.f32 %0, %1;" : "=r"(r) : "f"(x));
    return __uint_as_float(r);
}

__device__ __forceinline__ uint32_t smem_u32(const void* p) {
    uint32_t a;
    asm("{ .reg .u64 t; cvta.to.shared.u64 t, %1; cvt.u32.u64 %0, t; }" : "=r"(a) : "l"(p));
    return a;
}

__device__ __forceinline__ void cp_async16(uint32_t saddr, const void* gptr) {
    asm volatile("cp.async.cg.shared.global [%0], [%1], 16;" :: "r"(saddr), "l"(gptr));
}
#define CP_COMMIT() asm volatile("cp.async.commit_group;" ::: "memory")
#define CP_WAIT(n)  asm volatile("cp.async.wait_group %0;" :: "n"(n) : "memory")

// mma.sync m16n8k8 row.col f32 += tf32*tf32
// A frag: a0=(g,tg) a1=(g+8,tg) a2=(g,tg+4) a3=(g+8,tg+4)
// B frag: b0=(k=tg,n=g) b1=(k=tg+4,n=g)
// C frag: c0=(g,2tg) c1=(g,2tg+1) c2=(g+8,2tg) c3=(g+8,2tg+1)
__device__ __forceinline__ void mma_tf32(float* c, const float* a, const float* b) {
    asm volatile(
        "mma.sync.aligned.m16n8k8.row.col.f32.tf32.tf32.f32 "
        "{%0,%1,%2,%3}, {%4,%5,%6,%7}, {%8,%9}, {%0,%1,%2,%3};\n"
        : "+f"(c[0]), "+f"(c[1]), "+f"(c[2]), "+f"(c[3])
        : "r"(__float_as_uint(a[0])), "r"(__float_as_uint(a[1])),
          "r"(__float_as_uint(a[2])), "r"(__float_as_uint(a[3])),
          "r"(__float_as_uint(b[0])), "r"(__float_as_uint(b[1])));
}

// ---------------------------------------------------------------------------
// Prep: round x / weights to tf32 once (layout unchanged [k][n])
// ---------------------------------------------------------------------------
__global__ void prep_x_kernel(const float* __restrict__ x) {
    int i = blockIdx.x * blockDim.x + threadIdx.x;
    float4 v = ((const float4*)x)[i];
    v.x = to_tf32(v.x); v.y = to_tf32(v.y); v.z = to_tf32(v.z); v.w = to_tf32(v.w);
    ((float4*)g_xr)[i] = v;
}

__global__ void prep_w_kernel(const float* __restrict__ Wq, const float* __restrict__ Wk,
                              const float* __restrict__ Wv, const float* __restrict__ Wo) {
    int z = blockIdx.y;
    const float* W = (z == 0) ? Wq : (z == 1) ? Wk : (z == 2) ? Wv : Wo;
    int i = blockIdx.x * blockDim.x + threadIdx.x;
    float4 v = ((const float4*)W)[i];
    v.x = to_tf32(v.x); v.y = to_tf32(v.y); v.z = to_tf32(v.z); v.w = to_tf32(v.w);
    ((float4*)(g_wt + (size_t)z * DMODEL * DMODEL))[i] = v;
}

// ---------------------------------------------------------------------------
// Pipelined tf32 GEMM:  C[4096,1024] = A[4096,1024] @ W[1024,1024]
// CTA tile 128x256x64, 2-stage cp.async ring, 512 threads (16 warps, 2m x 8n,
// warp tile 64x32). 16 iterations, next chunk in flight during compute.
// qkv_mode=1: A=g_xr, W=g_wt[z]; z=0/1 -> g_q/g_k (dh PM8-permuted);
//             z=2 -> g_v transposed [bh][dh][t] (t PM8-permuted). tf32-rounded.
// qkv_mode=0: A=g_att, W=g_wt[3], dst=out row-major, full fp32.
// ---------------------------------------------------------------------------
#define GBM 128
#define GBN 256
#define GBK 64
#define ASTR 68          // 64 + 4 pad: (4g+tg) banks distinct for A-frag reads
#define BSTR 264         // (8tg+g) banks distinct for B-frag reads
#define NSTAGE 2
#define A_STAGE (GBM * ASTR)                    // 8704 floats
#define B_STAGE (GBK * BSTR)                    // 16896 floats
#define STAGE_FLOATS (A_STAGE + B_STAGE)        // 25600 floats
#define GEMM_SMEM (NSTAGE * STAGE_FLOATS * 4)   // 204800 bytes

__global__ __launch_bounds__(512, 1)
void gemm_tf32_pipe_kernel(float* __restrict__ out, int qkv_mode)
{
    extern __shared__ float sm[];
    const uint32_t sb = smem_u32(sm);

    const int tid = threadIdx.x;
    const int warp = tid >> 5, lane = tid & 31;
    const int g = lane >> 2, tg = lane & 3;
    const int wm = (warp & 1) * 64;       // 2 warps along M
    const int wn = (warp >> 1) * 32;      // 8 warps along N
    const int z = blockIdx.z;
    const int row0 = blockIdx.y * GBM;
    const int col0 = blockIdx.x * GBN;

    const float* A  = qkv_mode ? g_xr : g_att;
    const float* Wt = g_wt + (size_t)(qkv_mode ? z : 3) * DMODEL * DMODEL;

    float acc[4][4][4];
#pragma unroll
    for (int mi = 0; mi < 4; mi++)
#pragma unroll
        for (int ni = 0; ni < 4; ni++)
#pragma unroll
            for (int i = 0; i < 4; i++) acc[mi][ni][i] = 0.f;

    // ---- async chunk loader (512 threads), K-chunk of 64 ----
    auto load_chunk = [&](int c, int s) {
        const int kt = c * GBK;
        const uint32_t abase = sb + (uint32_t)(s * STAGE_FLOATS) * 4;
        const uint32_t bbase = abase + A_STAGE * 4;
#pragma unroll
        for (int it = 0; it < 4; it++) {
            int i = tid + it * 512;
            int row = i >> 4, seg = i & 15;
            cp_async16(abase + (uint32_t)(row * ASTR + seg * 4) * 4,
                       A + (size_t)(row0 + row) * DMODEL + kt + seg * 4);
        }
#pragma unroll
        for (int it = 0; it < 8; it++) {
            int i = tid + it * 512;
            int row = i >> 6, seg = i & 63;
            cp_async16(bbase + (uint32_t)(row * BSTR + seg * 4) * 4,
                       Wt + (size_t)(kt + row) * DMODEL + col0 + seg * 4);
        }
        CP_COMMIT();
    };

    // ---- compute one 64-deep K-chunk from stage s ----
    auto compute_chunk = [&](int s) {
        const float* As_ = sm + s * STAGE_FLOATS;
        const float* Bs_ = As_ + A_STAGE;
#pragma unroll
        for (int ks = 0; ks < 8; ks++) {
            float a[4][4], b[4][2];
#pragma unroll
            for (int mi = 0; mi < 4; mi++) {
                int r = wm + mi * 16 + g;
                a[mi][0] = As_[r * ASTR + ks * 8 + tg];
                a[mi][1] = As_[(r + 8) * ASTR + ks * 8 + tg];
                a[mi][2] = As_[r * ASTR + ks * 8 + tg + 4];
                a[mi][3] = As_[(r + 8) * ASTR + ks * 8 + tg + 4];
            }
#pragma unroll
            for (int ni = 0; ni < 4; ni++) {
                int c = wn + ni * 8 + g;
                b[ni][0] = Bs_[(ks * 8 + tg) * BSTR + c];
                b[ni][1] = Bs_[(ks * 8 + tg + 4) * BSTR + c];
            }
#pragma unroll
            for (int mi = 0; mi < 4; mi++)
#pragma unroll
                for (int ni = 0; ni < 4; ni++)
                    mma_tf32(acc[mi][ni], a[mi], b[ni]);
        }
    };

    const int NCHUNK = DMODEL / GBK;   // 16
    load_chunk(0, 0);

    for (int i = 0; i < NCHUNK; i++) {
        if (i + 1 < NCHUNK) { load_chunk(i + 1, (i + 1) & 1); CP_WAIT(1); }
        else                { CP_WAIT(0); }
        __syncthreads();                 // chunk i visible to all warps
        compute_chunk(i & 1);
        __syncthreads();                 // stage free before next overwrite
    }

    // ---- epilogue ----
#pragma unroll
    for (int mi = 0; mi < 4; mi++) {
        const int r0 = row0 + wm + mi * 16 + g;
        const int r1 = r0 + 8;
#pragma unroll
        for (int ni = 0; ni < 4; ni++) {
            const int c = col0 + wn + ni * 8 + 2 * tg;
            if (qkv_mode) {
                const int hh = c >> 6, dh = c & (DHEAD - 1);
                const int b0 = r0 >> 11, t0 = r0 & (T_SEQ - 1);
                const int b1 = r1 >> 11, t1 = r1 & (T_SEQ - 1);
                float v00 = to_tf32(acc[mi][ni][0]), v01 = to_tf32(acc[mi][ni][1]);
                float v10 = to_tf32(acc[mi][ni][2]), v11 = to_tf32(acc[mi][ni][3]);
                if (z == 2) {
                    // V transposed [bh][dh][t'], t PM8-permuted within 8-groups
                    const int tp0 = (t0 & ~7) | PM8(t0 & 7);
                    const int tp1 = (t1 & ~7) | PM8(t1 & 7);
                    float* base0 = g_v + ((size_t)(b0 * NHEAD + hh) * DHEAD + dh) * T_SEQ;
                    float* base1 = g_v + ((size_t)(b1 * NHEAD + hh) * DHEAD + dh) * T_SEQ;
                    base0[tp0]         = v00;
                    base0[T_SEQ + tp0] = v01;   // dh+1 row
                    base1[tp1]         = v10;
                    base1[T_SEQ + tp1] = v11;
                } else {
                    // Q/K: [bh][t][dh'], dh PM8-permuted within 8-groups
                    float* dst = (z == 0) ? g_q : g_k;
                    const int dp0 = (dh & ~7) | PM8(dh & 7);
                    const int dp1 = (dh & ~7) | PM8((dh + 1) & 7);
                    float* p0 = dst + ((size_t)(b0 * NHEAD + hh) * T_SEQ + t0) * DHEAD;
                    float* p1 = dst + ((size_t)(b1 * NHEAD + hh) * T_SEQ + t1) * DHEAD;
                    p0[dp0] = v00; p0[dp1] = v01;
                    p1[dp0] = v10; p1[dp1] = v11;
                }
            } else {
                float2 v0 = make_float2(acc[mi][ni][0], acc[mi][ni][1]);
                float2 v1 = make_float2(acc[mi][ni][2], acc[mi][ni][3]);
                *(float2*)&out[(size_t)r0 * DMODEL + c] = v0;
                *(float2*)&out[(size_t)r1 * DMODEL + c] = v1;
            }
        }
    }
}

// ---------------------------------------------------------------------------
// Flash attention (causal), tf32 mma.sync, fp32 online softmax.
// R9 structure: 256 threads, Q tile 128 (8 warps x 16 rows), KV tile 64,
// single-buffer KV, paired q-tiles (i, 15-i), 2 CTAs/SM.
// NEW: PM8 pair-interleaved layouts -> ALL fragment gathers are float2 LDS:
//   Q/K: dh-dim permuted (baked in gmem);  V: transposed + key-dim permuted;
//   P: stored at permuted key positions.  All strides 72 (==8 mod 32):
//   conflict-free float2 loads per half-warp.
// ---------------------------------------------------------------------------
#define QS 72
#define ATTN_SMEM ((128 * QS + 64 * QS + 64 * QS + 128 * QS) * 4)  // 110592

__global__ __launch_bounds__(256, 2)
void attn_kernel()
{
    extern __shared__ float sm[];
    float* Qs = sm;                      // 128 x 72  (q-rows x dh-permuted)
    float* Ks = Qs + 128 * QS;           // 64 x 72   (keys x dh-permuted)
    float* Vt = Ks + 64 * QS;            // 64 x 72   (dh x keys-permuted)
    float* Ps = Vt + 64 * QS;            // 128 x 72  (q-rows x keys-permuted)
    const uint32_t sb = smem_u32(sm);
    const uint32_t kb = sb + (uint32_t)(128 * QS) * 4;
    const uint32_t vb = kb + (uint32_t)(64 * QS) * 4;

    const int b = blockIdx.z, h = blockIdx.y;
    const int bh = b * NHEAD + h;
    const float* qptr  = g_q + (size_t)bh * T_SEQ * DHEAD;
    const float* kptr  = g_k + (size_t)bh * T_SEQ * DHEAD;
    const float* vtptr = g_v + (size_t)bh * DHEAD * T_SEQ;   // [dh][t']

    const int tid = threadIdx.x;
    const int warp = tid >> 5, lane = tid & 31;
    const int g = lane >> 2, tg = lane & 3;
    const int wm = warp * 16;
    const int p0 = PM8(2 * tg);          // store pos of key 2tg within 8-group
    const int p1 = PM8(2 * tg + 1);      // store pos of key 2tg+1

    for (int rep = 0; rep < 2; rep++) {
        const int qt = rep ? (T_SEQ / 128 - 1 - (int)blockIdx.x) : (int)blockIdx.x;
        const int q0 = qt * 128;

        __syncthreads();   // previous rep fully done with smem

        // async Q tile load: 128 rows x 16 segs = 2048, 8 per thread
#pragma unroll
        for (int it = 0; it < 8; it++) {
            int i = tid + it * 256;
            int row = i >> 4, seg = i & 15;
            cp_async16(sb + (uint32_t)(row * QS + seg * 4) * 4,
                       qptr + (size_t)(q0 + row) * DHEAD + seg * 4);
        }
        CP_COMMIT();

        float o[8][4];
#pragma unroll
        for (int ni = 0; ni < 8; ni++)
#pragma unroll
            for (int i = 0; i < 4; i++) o[ni][i] = 0.f;
        float m0 = -1e30f, m1 = -1e30f, l0 = 0.f, l1 = 0.f;

        const int jn = q0 / 64 + 2;      // KV tiles for this q-tile
        const int qrow0 = q0 + wm + g;
        const int qrow1 = qrow0 + 8;

        for (int j = 0; j < jn; j++) {
            if (j) __syncthreads();      // prior PV reads of Ks/Vt done
            // async K / Vt tile loads: 64 rows x 16 segs each, 4+4 per thread
#pragma unroll
            for (int it = 0; it < 4; it++) {
                int i = tid + it * 256;
                int row = i >> 4, seg = i & 15;
                cp_async16(kb + (uint32_t)(row * QS + seg * 4) * 4,
                           kptr + (size_t)(j * 64 + row) * DHEAD + seg * 4);
                cp_async16(vb + (uint32_t)(row * QS + seg * 4) * 4,
                           vtptr + (size_t)row * T_SEQ + j * 64 + seg * 4);
            }
            CP_COMMIT();
            CP_WAIT(0);
            __syncthreads();

            // S = Q @ K^T  (warp: 16 q-rows x 64 keys), float2 fragment loads
            float s[8][4];
#pragma unroll
            for (int ni = 0; ni < 8; ni++)
#pragma unroll
                for (int i = 0; i < 4; i++) s[ni][i] = 0.f;

#pragma unroll
            for (int ks = 0; ks < 8; ks++) {
                float2 qa0 = *(float2*)&Qs[(wm + g) * QS + ks * 8 + 2 * tg];
                float2 qa1 = *(float2*)&Qs[(wm + g + 8) * QS + ks * 8 + 2 * tg];
                float a[4] = {qa0.x, qa1.x, qa0.y, qa1.y};
#pragma unroll
                for (int ni = 0; ni < 8; ni++) {
                    float2 kbv = *(float2*)&Ks[(ni * 8 + g) * QS + ks * 8 + 2 * tg];
                    float bf[2] = {kbv.x, kbv.y};
                    mma_tf32(s[ni], a, bf);
                }
            }

            // scale + causal mask (s[ni][c] = key ni*8+2tg+(c&1), unchanged)
            const float scale = 0.125f;  // 1/sqrt(64)
#pragma unroll
            for (int ni = 0; ni < 8; ni++) {
                int kc = j * 64 + ni * 8 + 2 * tg;
                s[ni][0] = (kc     > qrow0) ? -1e30f : s[ni][0] * scale;
                s[ni][1] = (kc + 1 > qrow0) ? -1e30f : s[ni][1] * scale;
                s[ni][2] = (kc     > qrow1) ? -1e30f : s[ni][2] * scale;
                s[ni][3] = (kc + 1 > qrow1) ? -1e30f : s[ni][3] * scale;
            }

            // online softmax (4 lanes per row: xor 1,2)
            float mx0 = -1e30f, mx1 = -1e30f;
#pragma unroll
            for (int ni = 0; ni < 8; ni++) {
                mx0 = fmaxf(mx0, fmaxf(s[ni][0], s[ni][1]));
                mx1 = fmaxf(mx1, fmaxf(s[ni][2], s[ni][3]));
            }
            mx0 = fmaxf(mx0, __shfl_xor_sync(0xffffffffu, mx0, 1));
            mx0 = fmaxf(mx0, __shfl_xor_sync(0xffffffffu, mx0, 2));
            mx1 = fmaxf(mx1, __shfl_xor_sync(0xffffffffu, mx1, 1));
            mx1 = fmaxf(mx1, __shfl_xor_sync(0xffffffffu, mx1, 2));

            float mn0 = fmaxf(m0, mx0), mn1 = fmaxf(m1, mx1);
            float al0 = __expf(m0 - mn0), al1 = __expf(m1 - mn1);
            m0 = mn0; m1 = mn1;

            float sum0 = 0.f, sum1 = 0.f;
#pragma unroll
            for (int ni = 0; ni < 8; ni++) {
                float e00 = __expf(s[ni][0] - m0), e01 = __expf(s[ni][1] - m0);
                float e10 = __expf(s[ni][2] - m1), e11 = __expf(s[ni][3] - m1);
                sum0 += e00 + e01; sum1 += e10 + e11;
                // store at PM8-permuted key positions (matches Vt layout)
                Ps[(wm + g) * QS + ni * 8 + p0]     = to_tf32(e00);
                Ps[(wm + g) * QS + ni * 8 + p1]     = to_tf32(e01);
                Ps[(wm + g + 8) * QS + ni * 8 + p0] = to_tf32(e10);
                Ps[(wm + g + 8) * QS + ni * 8 + p1] = to_tf32(e11);
            }
            sum0 += __shfl_xor_sync(0xffffffffu, sum0, 1);
            sum0 += __shfl_xor_sync(0xffffffffu, sum0, 2);
            sum1 += __shfl_xor_sync(0xffffffffu, sum1, 1);
            sum1 += __shfl_xor_sync(0xffffffffu, sum1, 2);
            l0 = l0 * al0 + sum0;
            l1 = l1 * al1 + sum1;

#pragma unroll
            for (int ni = 0; ni < 8; ni++) {
                o[ni][0] *= al0; o[ni][1] *= al0;
                o[ni][2] *= al1; o[ni][3] *= al1;
            }
            __syncwarp();                // P rows are warp-private

            // O += P @ V  (float2 fragment loads from Ps and Vt)
#pragma unroll
            for (int ks = 0; ks < 8; ks++) {
                float2 pa0 = *(float2*)&Ps[(wm + g) * QS + ks * 8 + 2 * tg];
                float2 pa1 = *(float2*)&Ps[(wm + g + 8) * QS + ks * 8 + 2 * tg];
                float a[4] = {pa0.x, pa1.x, pa0.y, pa1.y};
#pragma unroll
                for (int ni = 0; ni < 8; ni++) {
                    float2 vbv = *(float2*)&Vt[(ni * 8 + g) * QS + ks * 8 + 2 * tg];
                    float bf[2] = {vbv.x, vbv.y};
                    mma_tf32(o[ni], a, bf);
                }
            }
        }

        // epilogue: normalize, tf32-round, scatter to [B*T, D] (unpermuted)
        const float inv0 = 1.f / l0, inv1 = 1.f / l1;
#pragma unroll
        for (int ni = 0; ni < 8; ni++) {
            int c = h * DHEAD + ni * 8 + 2 * tg;
            g_att[((size_t)b * T_SEQ + qrow0) * DMODEL + c]     = to_tf32(o[ni][0] * inv0);
            g_att[((size_t)b * T_SEQ + qrow0) * DMODEL + c + 1] = to_tf32(o[ni][1] * inv0);
            g_att[((size_t)b * T_SEQ + qrow1) * DMODEL + c]     = to_tf32(o[ni][2] * inv1);
            g_att[((size_t)b * T_SEQ + qrow1) * DMODEL + c + 1] = to_tf32(o[ni][3] * inv1);
        }
    }
}

// ---------------------------------------------------------------------------
// kernel_launch: x, mask(causal hard-coded), Wq, Wk, Wv, Wo
// ---------------------------------------------------------------------------
extern "C" void kernel_launch(void* const* d_in, const int* in_sizes, int n_in,
                              void* d_out, int out_size)
{
    (void)in_sizes; (void)n_in; (void)out_size;
    const float* x  = (const float*)d_in[0];
    const float* Wq = (const float*)d_in[2];
    const float* Wk = (const float*)d_in[3];
    const float* Wv = (const float*)d_in[4];
    const float* Wo = (const float*)d_in[5];
    float* out = (float*)d_out;

    // prep: tf32-round inputs once
    prep_x_kernel<<<(MROWS * DMODEL / 4) / 256, 256>>>(x);
    prep_w_kernel<<<dim3((DMODEL * DMODEL / 4) / 256, 4), 256>>>(Wq, Wk, Wv, Wo);

    cudaFuncSetAttribute(gemm_tf32_pipe_kernel,
                         cudaFuncAttributeMaxDynamicSharedMemorySize, GEMM_SMEM);

    // fused QKV projections
    gemm_tf32_pipe_kernel<<<dim3(DMODEL / GBN, MROWS / GBM, 3), 512, GEMM_SMEM>>>(nullptr, 1);

    cudaFuncSetAttribute(attn_kernel,
                         cudaFuncAttributeMaxDynamicSharedMemorySize, ATTN_SMEM);
    attn_kernel<<<dim3(T_SEQ / 256, NHEAD, BATCH), 256, ATTN_SMEM>>>();

    // output projection
    gemm_tf32_pipe_kernel<<<dim3(DMODEL / GBN, MROWS / GBM, 1), 512, GEMM_SMEM>>>(out, 0);
}